// round 10
// baseline (speedup 1.0000x reference)
#include <cuda_runtime.h>
#include <math.h>

// RZ_50259707298063: y_re[s,b] = xr[s,b]*cos(phi_s) - xi[s,b]*sin(phi_s)
// phi_s = sum_i ( bit(s, nwires-1-i) ? +theta_i/2 : -theta_i/2 )
// Output = float32 real part (established round 7).
//
// R9: R8 fused kernel was latency-bound at occ=39% (grid=512 too small,
// all pipes idle). Halve per-thread work to 8 floats -> grid 1024,
// occ ~85%, 2x loads in flight.

#define TPB 256

__global__ void __launch_bounds__(TPB) rz_fused8(
    const float4* __restrict__ xr,
    const float4* __restrict__ xi,
    const float* __restrict__ angle,
    int nwires,
    int vecs_per_row,        // batch/4
    int threads_per_row,     // batch/8
    int rows_per_block,      // TPB / threads_per_row
    float4* __restrict__ out)
{
    __shared__ float2 ph[TPB];

    const int tid = threadIdx.x;

    if (tid < rows_per_block) {
        const long s = (long)blockIdx.x * rows_per_block + tid;
        float phi = 0.0f;
        for (int i = 0; i < nwires; i++) {
            const float half = 0.5f * angle[i];
            phi += (((s >> (nwires - 1 - i)) & 1L) != 0) ? half : -half;
        }
        float sn, cs;
        sincosf(phi, &sn, &cs);
        ph[tid] = make_float2(cs, sn);
    }
    __syncthreads();

    const int r = tid / threads_per_row;
    const int c = tid % threads_per_row;
    const float2 p = ph[r];                      // warp-uniform broadcast

    const long row  = (long)blockIdx.x * rows_per_block + r;
    const long base = row * vecs_per_row + c;    // float4 index

    // Front-batched: 4 LDG.128 in flight before compute.
    float4 r0 = xr[base];
    float4 r1 = xr[base + threads_per_row];
    float4 i0 = xi[base];
    float4 i1 = xi[base + threads_per_row];

    float4 o0, o1;
    o0.x = fmaf(r0.x, p.x, -i0.x * p.y);
    o0.y = fmaf(r0.y, p.x, -i0.y * p.y);
    o0.z = fmaf(r0.z, p.x, -i0.z * p.y);
    o0.w = fmaf(r0.w, p.x, -i0.w * p.y);
    o1.x = fmaf(r1.x, p.x, -i1.x * p.y);
    o1.y = fmaf(r1.y, p.x, -i1.y * p.y);
    o1.z = fmaf(r1.z, p.x, -i1.z * p.y);
    o1.w = fmaf(r1.w, p.x, -i1.w * p.y);

    out[base] = o0;
    out[base + threads_per_row] = o1;
}

// Generic fallback (proven correct in round 7).
__global__ void __launch_bounds__(256) rz_real_scalar(
    const float* __restrict__ xr,
    const float* __restrict__ xi,
    const float* __restrict__ angle,
    int nwires, int batch, long n,
    float* __restrict__ out)
{
    const long stride = (long)gridDim.x * blockDim.x;
    for (long e = (long)blockIdx.x * blockDim.x + threadIdx.x; e < n; e += stride) {
        const long s = e / batch;
        float phi = 0.0f;
        for (int i = 0; i < nwires; i++) {
            const float half = 0.5f * __ldg(&angle[i]);
            phi += (((s >> (nwires - 1 - i)) & 1L) != 0) ? half : -half;
        }
        float sn, cs;
        sincosf(phi, &sn, &cs);
        out[e] = fmaf(xr[e], cs, -xi[e] * sn);
    }
}

extern "C" void kernel_launch(void* const* d_in, const int* in_sizes, int n_in,
                              void* d_out, int out_size) {
    if (n_in < 3 || d_out == nullptr) return;

    // angle = smallest buffer; remaining two equal-size buffers, in index
    // order, are x_real then x_imag.
    int ai = 0;
    for (int i = 1; i < n_in; i++)
        if (in_sizes[i] < in_sizes[ai]) ai = i;

    const float* angle = (const float*)d_in[ai];
    const float* xr = nullptr;
    const float* xi = nullptr;
    long nelem = 0;
    for (int i = 0; i < n_in; i++) {
        if (i == ai) continue;
        if (xr == nullptr) { xr = (const float*)d_in[i]; nelem = in_sizes[i]; }
        else if (xi == nullptr && in_sizes[i] == (int)nelem)
            xi = (const float*)d_in[i];
    }
    if (!angle || !xr || !xi || nelem <= 0) return;

    int nwires = in_sizes[ai];
    if (nwires > 20) { nwires /= 4; nelem /= 4; }   // byte-count hedge
    if (nwires < 1 || nwires > 20) return;

    const long nstates = 1L << nwires;
    int batch = (int)(nelem / nstates);
    if (batch <= 0) batch = 1;

    // Output budget in floats (real part only).
    long n = nelem;
    if ((long)out_size < n) n = (long)out_size;

    const int threads_per_row = batch / 8;           // 8 floats per thread
    const bool fused_ok =
        (n == nelem) &&
        (batch % 8 == 0) &&
        (threads_per_row >= 1) && (threads_per_row <= TPB) &&
        (TPB % threads_per_row == 0) &&
        (nstates % (TPB / threads_per_row) == 0);

    if (fused_ok) {
        const int rows_per_block = TPB / threads_per_row;
        const int grid = (int)(nstates / rows_per_block);
        rz_fused8<<<grid, TPB>>>((const float4*)xr, (const float4*)xi, angle,
                                 nwires, batch / 4, threads_per_row,
                                 rows_per_block, (float4*)d_out);
    } else {
        rz_real_scalar<<<2048, 256>>>(xr, xi, angle, nwires, batch, n,
                                      (float*)d_out);
    }
}

// round 13
// speedup vs baseline: 1.0492x; 1.0492x over previous
#include <cuda_runtime.h>
#include <math.h>

// RZ_50259707298063: y_re[s,b] = xr[s,b]*cos(phi_s) - xi[s,b]*sin(phi_s)
// phi_s = sum_i ( bit(s, nwires-1-i) ? +theta_i/2 : -theta_i/2 )
// Output = float32 real part (established round 7).
//
// R10: R8/R9 were latency/queue-bound (~2TB/s, all pipes idle; front-batched
// LDG + per-block sincos prologue). Split: phase-table kernel + pure
// streaming kernel (1 float4 per thread, MLP_p1=2, no barrier, no sincos),
// with streaming cache hints on the bulk data.

#define MAX_STATES 65536   // up to 16 wires; 512 KB table

__device__ float2 g_phase[MAX_STATES];

__global__ void __launch_bounds__(256) phase_table_kernel(
    const float* __restrict__ angle, int nwires, int nstates)
{
    const int s = blockIdx.x * blockDim.x + threadIdx.x;
    if (s >= nstates) return;
    float phi = 0.0f;
    for (int i = 0; i < nwires; i++) {
        const float half = 0.5f * angle[i];
        phi += ((s >> (nwires - 1 - i)) & 1) ? half : -half;
    }
    float sn, cs;
    sincosf(phi, &sn, &cs);
    g_phase[s] = make_float2(cs, sn);
}

// Pure stream: v = float4 index; row = v >> log2_vpr (vecs_per_row = 2^k).
__global__ void __launch_bounds__(256) rz_stream(
    const float4* __restrict__ xr,
    const float4* __restrict__ xi,
    float4* __restrict__ out,
    int log2_vpr, long nvec)
{
    const long v = (long)blockIdx.x * blockDim.x + threadIdx.x;
    if (v >= nvec) return;

    const float4 r  = __ldcs(xr + v);     // streaming: no L2 retention
    const float4 im = __ldcs(xi + v);
    const float2 p  = g_phase[v >> log2_vpr];   // broadcast, L1/L2 cached

    float4 o;
    o.x = fmaf(r.x, p.x, -im.x * p.y);
    o.y = fmaf(r.y, p.x, -im.y * p.y);
    o.z = fmaf(r.z, p.x, -im.z * p.y);
    o.w = fmaf(r.w, p.x, -im.w * p.y);
    __stcs(out + v, o);
}

// Generic fallback (proven correct round 7).
__global__ void __launch_bounds__(256) rz_real_scalar(
    const float* __restrict__ xr,
    const float* __restrict__ xi,
    const float* __restrict__ angle,
    int nwires, int batch, long n,
    float* __restrict__ out)
{
    const long stride = (long)gridDim.x * blockDim.x;
    for (long e = (long)blockIdx.x * blockDim.x + threadIdx.x; e < n; e += stride) {
        const long s = e / batch;
        float phi = 0.0f;
        for (int i = 0; i < nwires; i++) {
            const float half = 0.5f * __ldg(&angle[i]);
            phi += (((s >> (nwires - 1 - i)) & 1L) != 0) ? half : -half;
        }
        float sn, cs;
        sincosf(phi, &sn, &cs);
        out[e] = fmaf(xr[e], cs, -xi[e] * sn);
    }
}

extern "C" void kernel_launch(void* const* d_in, const int* in_sizes, int n_in,
                              void* d_out, int out_size) {
    if (n_in < 3 || d_out == nullptr) return;

    // angle = smallest buffer; remaining two equal-size buffers, in index
    // order, are x_real then x_imag.
    int ai = 0;
    for (int i = 1; i < n_in; i++)
        if (in_sizes[i] < in_sizes[ai]) ai = i;

    const float* angle = (const float*)d_in[ai];
    const float* xr = nullptr;
    const float* xi = nullptr;
    long nelem = 0;
    for (int i = 0; i < n_in; i++) {
        if (i == ai) continue;
        if (xr == nullptr) { xr = (const float*)d_in[i]; nelem = in_sizes[i]; }
        else if (xi == nullptr && in_sizes[i] == (int)nelem)
            xi = (const float*)d_in[i];
    }
    if (!angle || !xr || !xi || nelem <= 0) return;

    int nwires = in_sizes[ai];
    if (nwires > 20) { nwires /= 4; nelem /= 4; }   // byte-count hedge
    if (nwires < 1 || nwires > 20) return;

    const long nstates = 1L << nwires;
    int batch = (int)(nelem / nstates);
    if (batch <= 0) batch = 1;

    // Output budget in floats (real part only).
    long n = nelem;
    if ((long)out_size < n) n = (long)out_size;

    // Fast path: batch/4 a power of two, full coverage, table fits.
    const int vpr = batch / 4;
    int log2_vpr = 0;
    while ((1 << log2_vpr) < vpr) log2_vpr++;

    const bool fused_ok =
        (n == nelem) && (batch % 4 == 0) && ((1 << log2_vpr) == vpr) &&
        (nstates <= MAX_STATES);

    if (fused_ok) {
        phase_table_kernel<<<(int)((nstates + 255) / 256), 256>>>(
            angle, nwires, (int)nstates);
        const long nvec = n / 4;
        rz_stream<<<(int)((nvec + 255) / 256), 256>>>(
            (const float4*)xr, (const float4*)xi, (float4*)d_out,
            log2_vpr, nvec);
    } else {
        rz_real_scalar<<<2048, 256>>>(xr, xi, angle, nwires, batch, n,
                                      (float*)d_out);
    }
}